// round 4
// baseline (speedup 1.0000x reference)
#include <cuda_runtime.h>
#include <cuda_fp16.h>
#include <cstdint>

// ===========================================================================
// Arch-feature detection: tcgen05 exists only on 'a'/'f' feature targets.
// ===========================================================================
#define HAS_TCGEN05 0
#if defined(__CUDA_ARCH__) && (__CUDA_ARCH__ >= 1000)
#  if defined(__CUDA_ARCH_FAMILY_SPECIFIC__) || defined(__CUDA_ARCH_SPECIFIC__)
#    undef HAS_TCGEN05
#    define HAS_TCGEN05 1
#  elif defined(__CUDA_ARCH_HAS_FEATURE__)
#    if __CUDA_ARCH_HAS_FEATURE__(SM103_ALL) || __CUDA_ARCH_HAS_FEATURE__(SM100_ALL)
#      undef HAS_TCGEN05
#      define HAS_TCGEN05 1
#    endif
#  endif
#endif

// Problem constants
#define M_DIM 8192
#define N_DIM 4096
#define K_DIM 4096
#define NOUT  128
#define KE    4224            // K + NOUT (outlier GEMM fused as extra K)

// tcgen05 GEMM tiling: effective CTA tile 256x256 = 2 m-tiles of 128 sharing B
#define TM 128                // rows per m-tile (per MMA dispatch)
#define MT 2                  // m-tiles per CTA
#define TN 256
#define CH_K 64
#define NCHUNK (KE / CH_K)    // 66
#define NSTAGE 3
#define A_STG_BYTES (MT * TM * 128)       // 32768
#define B_STG_BYTES (TN * 128)            // 32768
#define STG_BYTES   (A_STG_BYTES + B_STG_BYTES)   // 65536
#define CTRL_OFF    (NSTAGE * STG_BYTES)          // 196608
#define SMEM_TOTAL  (CTRL_OFF + 64)

#define IDESC ((1u << 4) | ((TN / 8) << 17) | ((TM / 16) << 24))
#define DESC_BASE ((uint64_t(2) << 61) | (uint64_t(1) << 46) | (uint64_t(64) << 32) | (uint64_t(1) << 16))

// Scratch fp16 operands (device globals — no runtime allocation)
__device__ __align__(128) __half g_Xe[(size_t)M_DIM * KE];
__device__ __align__(128) __half g_We[(size_t)N_DIM * KE];

// ---------------------------------------------------------------------------
// Prep kernels (fp32 -> fp16, dequant, outlier fusion) — arch-agnostic
// ---------------------------------------------------------------------------
__global__ void prep_x(const float* __restrict__ x) {
    const int per_row = KE / 4;
    int idx = blockIdx.x * blockDim.x + threadIdx.x;
    if (idx >= M_DIM * per_row) return;
    int m  = idx / per_row;
    int k4 = (idx - m * per_row) * 4;
    const float* src = x + (size_t)m * K_DIM + (k4 < K_DIM ? k4 : k4 - NOUT);
    float4 v = *(const float4*)src;
    __half2* dst = (__half2*)(g_Xe + (size_t)m * KE + k4);
    dst[0] = __floats2half2_rn(v.x, v.y);
    dst[1] = __floats2half2_rn(v.z, v.w);
}

__global__ void prep_w(const int* __restrict__ qw,
                       const float* __restrict__ scales,
                       const float* __restrict__ zeros,
                       const float* __restrict__ ow) {
    const int per_row = KE / 4;
    int idx = blockIdx.x * blockDim.x + threadIdx.x;
    if (idx >= N_DIM * per_row) return;
    int n  = idx / per_row;
    int k4 = (idx - n * per_row) * 4;
    __half2 h0, h1;
    if (k4 < K_DIM) {
        int4 q = *(const int4*)(qw + (size_t)n * K_DIM + k4);
        int g = k4 >> 7;
        float s = scales[g * N_DIM + n];
        float z = zeros[g * N_DIM + n];
        h0 = __floats2half2_rn((float)q.x * s + z, (float)q.y * s + z);
        h1 = __floats2half2_rn((float)q.z * s + z, (float)q.w * s + z);
    } else {
        float4 o = *(const float4*)(ow + (size_t)n * NOUT + (k4 - K_DIM));
        h0 = __floats2half2_rn(o.x, o.y);
        h1 = __floats2half2_rn(o.z, o.w);
    }
    __half2* dst = (__half2*)(g_We + (size_t)n * KE + k4);
    dst[0] = h0; dst[1] = h1;
}

// ===========================================================================
// Path A: tcgen05 GEMM (compiled only on 'a'/'f' feature targets)
// ===========================================================================
#if HAS_TCGEN05
__device__ __forceinline__ uint32_t smem_u32(const void* p) {
    return (uint32_t)__cvta_generic_to_shared(p);
}
__device__ __forceinline__ uint32_t elect_one() {
    uint32_t pred;
    asm volatile("{.reg .pred p; elect.sync _|p, 0xFFFFFFFF; selp.b32 %0, 1, 0, p;}"
                 : "=r"(pred));
    return pred;
}
__device__ __forceinline__ void mma_f16_ss(uint32_t d, uint64_t ad, uint64_t bd,
                                           uint32_t idesc, uint32_t accum) {
    asm volatile(
        "{.reg .pred p; setp.ne.u32 p, %5, 0;\n\t"
        "tcgen05.mma.cta_group::1.kind::f16 [%0], %1, %2, %3, {%4,%4,%4,%4}, p;}\n"
        :: "r"(d), "l"(ad), "l"(bd), "r"(idesc), "r"(0u), "r"(accum) : "memory");
}
__device__ __forceinline__ void mbar_wait(uint32_t addr, uint32_t parity) {
    asm volatile(
        "{.reg .pred P1;\n\t"
        "LAB_WAIT_%=:\n\t"
        "mbarrier.try_wait.parity.acquire.cta.shared::cta.b64 P1, [%0], %1, 0x989680;\n\t"
        "@P1 bra LAB_DONE_%=;\n\t"
        "bra LAB_WAIT_%=;\n\t"
        "LAB_DONE_%=:}\n"
        :: "r"(addr), "r"(parity) : "memory");
}
#endif

extern __shared__ __align__(1024) char smn[];

__global__ void __launch_bounds__(256, 1)
gemm_tc(const float* __restrict__ bias, float* __restrict__ y) {
#if HAS_TCGEN05
    const int tid  = threadIdx.x;
    const int w    = tid >> 5;
    const int lane = tid & 31;
    const int bm   = blockIdx.y * (MT * TM);   // 256 rows per CTA
    const int bn   = blockIdx.x * TN;

    const uint32_t sbase = smem_u32(smn);
    const uint32_t ctrl  = sbase + CTRL_OFF;

    if (w == 0) {
        asm volatile("tcgen05.alloc.cta_group::1.sync.aligned.shared::cta.b32 [%0], %1;"
                     :: "r"(ctrl), "r"(512u) : "memory");
        asm volatile("tcgen05.relinquish_alloc_permit.cta_group::1.sync.aligned;");
    }
    if (tid == 0) {
#pragma unroll
        for (int b = 0; b < NSTAGE; b++)
            asm volatile("mbarrier.init.shared.b64 [%0], 1;" :: "r"(ctrl + 8 + 8 * b) : "memory");
    }
    __syncthreads();
    uint32_t tmem;
    asm volatile("ld.shared.b32 %0, [%1];" : "=r"(tmem) : "r"(ctrl));

    const __half* Ag = g_Xe + (size_t)bm * KE;
    const __half* Bg = g_We + (size_t)bn * KE;

    // Load chunk c into buffer b: A 256 rows + B 256 rows, SW128 swizzle
    auto load = [&](int b, int c) {
        const int k0 = c * CH_K;
        const uint32_t aB = sbase + b * STG_BYTES;
        const uint32_t bB = aB + A_STG_BYTES;
#pragma unroll
        for (int i = 0; i < 8; i++) {                      // A: 2048 chunks / 256 thr
            int idx = tid + i * 256;
            int row = idx >> 3, cc = idx & 7;
            uint32_t dst = aB + (uint32_t)(row * 128 + ((cc ^ (row & 7)) << 4));
            const __half* src = Ag + (size_t)row * KE + k0 + cc * 8;
            asm volatile("cp.async.cg.shared.global [%0], [%1], 16;" :: "r"(dst), "l"(src));
        }
#pragma unroll
        for (int i = 0; i < 8; i++) {                      // B: 2048 chunks / 256 thr
            int idx = tid + i * 256;
            int row = idx >> 3, cc = idx & 7;
            uint32_t dst = bB + (uint32_t)(row * 128 + ((cc ^ (row & 7)) << 4));
            const __half* src = Bg + (size_t)row * KE + k0 + cc * 8;
            asm volatile("cp.async.cg.shared.global [%0], [%1], 16;" :: "r"(dst), "l"(src));
        }
    };

    // Prologue: stages 0,1
#pragma unroll
    for (int c = 0; c < 2; c++) {
        load(c, c);
        asm volatile("cp.async.commit_group;");
    }

    for (int ks = 0; ks < NCHUNK; ks++) {
        asm volatile("cp.async.wait_group 1;");
        __syncthreads();

        const int buf = ks % NSTAGE;
        if (w == 0) {
            asm volatile("fence.proxy.async.shared::cta;" ::: "memory");
            asm volatile("tcgen05.fence::after_thread_sync;" ::: "memory");
            if (elect_one()) {
                const uint32_t aAddr = sbase + buf * STG_BYTES;
                const uint64_t bd = DESC_BASE | (((aAddr + A_STG_BYTES) >> 4) & 0x3FFF);
#pragma unroll
                for (int mt = 0; mt < MT; mt++) {
                    const uint64_t ad = DESC_BASE | (((aAddr + mt * (TM * 128)) >> 4) & 0x3FFF);
                    const uint32_t d  = tmem + mt * TN;
#pragma unroll
                    for (int kk = 0; kk < 4; kk++)
                        mma_f16_ss(d, ad + kk * 2, bd + kk * 2, IDESC,
                                   (ks > 0 || kk > 0) ? 1u : 0u);
                }
                asm volatile(
                    "tcgen05.commit.cta_group::1.mbarrier::arrive::one.shared::cluster.b64 [%0];"
                    :: "r"(ctrl + 8 + 8 * buf) : "memory");
            }
        }

        // Load chunk ks+2 into buffer (ks+2)%3; previous occupant = chunk ks-1.
        if (ks + 2 < NCHUNK) {
            const int nb = (ks + 2) % NSTAGE;
            if (ks > 0)
                mbar_wait(ctrl + 8 + 8 * nb, (uint32_t)(((ks - 1) / NSTAGE) & 1));
            load(nb, ks + 2);
        }
        asm volatile("cp.async.commit_group;");
    }

    // Wait final MMA
    {
        const int lastc = NCHUNK - 1;
        mbar_wait(ctrl + 8 + 8 * (lastc % NSTAGE), (uint32_t)((lastc / NSTAGE) & 1));
    }
    asm volatile("tcgen05.fence::after_thread_sync;" ::: "memory");

    // Epilogue: warps 0-3 read D0 (m-tile 0), warps 4-7 read D1 (m-tile 1).
    {
        const uint32_t warp_off = (uint32_t)((tid & 127) >> 5) << 21;
        const int mt = w >> 2;                       // 0 or 1
        const int m  = bm + mt * TM + ((w & 3) << 5) + lane;
        float* yrow = y + (size_t)m * N_DIM;
        const uint32_t dBase = tmem + (uint32_t)(mt * TN) + warp_off;
#pragma unroll
        for (int cb = 0; cb < TN; cb += 32) {
            uint32_t r[32];
            asm volatile(
                "tcgen05.ld.sync.aligned.32x32b.x32.b32 "
                "{%0,%1,%2,%3,%4,%5,%6,%7,%8,%9,%10,%11,%12,%13,%14,%15,"
                "%16,%17,%18,%19,%20,%21,%22,%23,%24,%25,%26,%27,%28,%29,%30,%31}, [%32];"
                : "=r"(r[0]), "=r"(r[1]), "=r"(r[2]), "=r"(r[3]), "=r"(r[4]), "=r"(r[5]),
                  "=r"(r[6]), "=r"(r[7]), "=r"(r[8]), "=r"(r[9]), "=r"(r[10]), "=r"(r[11]),
                  "=r"(r[12]), "=r"(r[13]), "=r"(r[14]), "=r"(r[15]), "=r"(r[16]), "=r"(r[17]),
                  "=r"(r[18]), "=r"(r[19]), "=r"(r[20]), "=r"(r[21]), "=r"(r[22]), "=r"(r[23]),
                  "=r"(r[24]), "=r"(r[25]), "=r"(r[26]), "=r"(r[27]), "=r"(r[28]), "=r"(r[29]),
                  "=r"(r[30]), "=r"(r[31])
                : "r"(dBase + (uint32_t)cb));
            asm volatile("tcgen05.wait::ld.sync.aligned;" ::: "memory");
            const int col0 = bn + cb;
#pragma unroll
            for (int q = 0; q < 8; q++) {
                float4 bv = *(const float4*)(bias + col0 + q * 4);
                float4 o;
                o.x = __uint_as_float(r[q * 4 + 0]) + bv.x;
                o.y = __uint_as_float(r[q * 4 + 1]) + bv.y;
                o.z = __uint_as_float(r[q * 4 + 2]) + bv.z;
                o.w = __uint_as_float(r[q * 4 + 3]) + bv.w;
                *(float4*)(yrow + col0 + q * 4) = o;
            }
        }
    }

    __syncthreads();
    if (w == 0) {
        asm volatile("tcgen05.dealloc.cta_group::1.sync.aligned.b32 %0, %1;"
                     :: "r"(tmem), "r"(512u));
    }
#endif  // HAS_TCGEN05
}

// ===========================================================================
// Path B: proven mma.sync fallback (compiled only when tcgen05 is unavailable)
// ===========================================================================
__global__ __launch_bounds__(256, 2) void gemm_f16(const float* __restrict__ bias,
                                                   float* __restrict__ y) {
#if !HAS_TCGEN05
    __shared__ __align__(16) __half As[3][128 * 32];
    __shared__ __align__(16) __half Bs[3][128 * 32];

    const int t    = threadIdx.x;
    const int lane = t & 31;
    const int w    = t >> 5;
    const int bm   = blockIdx.y << 7;
    const int bn   = blockIdx.x << 7;
    const int wm   = (w >> 2) << 6;
    const int wn   = (w & 3) << 5;

    const __half* Ag = g_Xe + (size_t)bm * KE;
    const __half* Bg = g_We + (size_t)bn * KE;

    const int lr = t >> 2;
    const int lc = t & 3;

    float acc[4][4][4];
#pragma unroll
    for (int i = 0; i < 4; i++)
#pragma unroll
        for (int j = 0; j < 4; j++)
#pragma unroll
            for (int r = 0; r < 4; r++) acc[i][j][r] = 0.f;

    unsigned sA = (unsigned)__cvta_generic_to_shared(As);
    unsigned sB = (unsigned)__cvta_generic_to_shared(Bs);

    auto swz = [](int row, int chunk) {
        return (row << 5) + ((chunk ^ ((row >> 1) & 3)) << 3);
    };

    auto load_stage = [&](int buf, int ks) {
        int k0 = ks << 5;
#pragma unroll
        for (int i = 0; i < 2; i++) {
            int row = lr + (i << 6);
            unsigned da = sA + (unsigned)((buf * 4096 + swz(row, lc)) << 1);
            const __half* ga = Ag + (size_t)row * KE + k0 + (lc << 3);
            asm volatile("cp.async.cg.shared.global [%0], [%1], 16;\n" ::"r"(da), "l"(ga));
            unsigned db = sB + (unsigned)((buf * 4096 + swz(row, lc)) << 1);
            const __half* gb = Bg + (size_t)row * KE + k0 + (lc << 3);
            asm volatile("cp.async.cg.shared.global [%0], [%1], 16;\n" ::"r"(db), "l"(gb));
        }
    };

    const int NSTEP = KE / 32;
    load_stage(0, 0);
    asm volatile("cp.async.commit_group;\n");
    load_stage(1, 1);
    asm volatile("cp.async.commit_group;\n");

    const int a_row  = wm + (lane & 15);
    const int a_cofs = lane >> 4;
    const int b_row  = wn + (lane & 7) + ((lane >> 4) << 3);
    const int b_cofs = (lane >> 3) & 1;

    for (int ks = 0; ks < NSTEP; ks++) {
        asm volatile("cp.async.wait_group 1;\n");
        __syncthreads();
        int buf = ks % 3;
        if (ks + 2 < NSTEP) load_stage((ks + 2) % 3, ks + 2);
        asm volatile("cp.async.commit_group;\n");

        unsigned baseA = sA + (unsigned)(buf * 8192);
        unsigned baseB = sB + (unsigned)(buf * 8192);

#pragma unroll
        for (int p = 0; p < 2; p++) {
            unsigned a[4][4];
#pragma unroll
            for (int i = 0; i < 4; i++) {
                int row = a_row + (i << 4);
                int chunk = (p << 1) + a_cofs;
                unsigned addr = baseA + (unsigned)(swz(row, chunk) << 1);
                asm volatile(
                    "ldmatrix.sync.aligned.m8n8.x4.shared.b16 {%0,%1,%2,%3}, [%4];\n"
                    : "=r"(a[i][0]), "=r"(a[i][1]), "=r"(a[i][2]), "=r"(a[i][3])
                    : "r"(addr));
            }
            unsigned b[4][2];
#pragma unroll
            for (int jj = 0; jj < 2; jj++) {
                int row = b_row + (jj << 4);
                int chunk = (p << 1) + b_cofs;
                unsigned addr = baseB + (unsigned)(swz(row, chunk) << 1);
                unsigned r0, r1, r2, r3;
                asm volatile(
                    "ldmatrix.sync.aligned.m8n8.x4.shared.b16 {%0,%1,%2,%3}, [%4];\n"
                    : "=r"(r0), "=r"(r1), "=r"(r2), "=r"(r3)
                    : "r"(addr));
                b[jj * 2][0] = r0; b[jj * 2][1] = r1;
                b[jj * 2 + 1][0] = r2; b[jj * 2 + 1][1] = r3;
            }
#pragma unroll
            for (int i = 0; i < 4; i++)
#pragma unroll
                for (int j = 0; j < 4; j++)
                    asm volatile(
                        "mma.sync.aligned.m16n8k16.row.col.f32.f16.f16.f32 "
                        "{%0,%1,%2,%3}, {%4,%5,%6,%7}, {%8,%9}, {%0,%1,%2,%3};\n"
                        : "+f"(acc[i][j][0]), "+f"(acc[i][j][1]),
                          "+f"(acc[i][j][2]), "+f"(acc[i][j][3])
                        : "r"(a[i][0]), "r"(a[i][1]), "r"(a[i][2]), "r"(a[i][3]),
                          "r"(b[j][0]), "r"(b[j][1]));
        }
    }

#pragma unroll
    for (int i = 0; i < 4; i++) {
        int row = bm + wm + (i << 4) + (lane >> 2);
#pragma unroll
        for (int j = 0; j < 4; j++) {
            int col = bn + wn + (j << 3) + ((lane & 3) << 1);
            float2 bb = *(const float2*)(bias + col);
            float2 o0 = make_float2(acc[i][j][0] + bb.x, acc[i][j][1] + bb.y);
            float2 o1 = make_float2(acc[i][j][2] + bb.x, acc[i][j][3] + bb.y);
            *(float2*)(y + (size_t)row * N_DIM + col)       = o0;
            *(float2*)(y + (size_t)(row + 8) * N_DIM + col) = o1;
        }
    }
#endif  // !HAS_TCGEN05
}

// ---------------------------------------------------------------------------
extern "C" void kernel_launch(void* const* d_in, const int* in_sizes, int n_in,
                              void* d_out, int out_size) {
    const float* x      = (const float*)d_in[0];
    const int*   qw     = (const int*)d_in[1];
    const float* scales = (const float*)d_in[2];
    const float* zeros  = (const float*)d_in[3];
    const float* ow     = (const float*)d_in[4];
    const float* bias   = (const float*)d_in[5];
    float*       y      = (float*)d_out;

    prep_x<<<(M_DIM * (KE / 4)) / 256, 256>>>(x);
    prep_w<<<(N_DIM * (KE / 4)) / 256, 256>>>(qw, scales, zeros, ow);

    // Exactly one of these does work, decided at device-code compile time.
    cudaFuncSetAttribute(gemm_tc, cudaFuncAttributeMaxDynamicSharedMemorySize, SMEM_TOTAL);
    dim3 gridT(N_DIM / TN, M_DIM / (MT * TM));   // (16, 32)
    gemm_tc<<<gridT, 256, SMEM_TOTAL>>>(bias, y);

    dim3 gridF(N_DIM / 128, M_DIM / 128);        // (32, 64)
    gemm_f16<<<gridF, 256>>>(bias, y);
}

// round 5
// speedup vs baseline: 1.0629x; 1.0629x over previous
#include <cuda_runtime.h>
#include <cuda_fp16.h>
#include <cstdint>

// ===========================================================================
// Arch-feature detection: tcgen05 exists only on 'a'/'f' feature targets.
// ===========================================================================
#define HAS_TCGEN05 0
#if defined(__CUDA_ARCH__) && (__CUDA_ARCH__ >= 1000)
#  if defined(__CUDA_ARCH_FAMILY_SPECIFIC__) || defined(__CUDA_ARCH_SPECIFIC__)
#    undef HAS_TCGEN05
#    define HAS_TCGEN05 1
#  elif defined(__CUDA_ARCH_HAS_FEATURE__)
#    if __CUDA_ARCH_HAS_FEATURE__(SM103_ALL) || __CUDA_ARCH_HAS_FEATURE__(SM100_ALL)
#      undef HAS_TCGEN05
#      define HAS_TCGEN05 1
#    endif
#  endif
#endif

// Problem constants
#define M_DIM 8192
#define N_DIM 4096
#define K_DIM 4096
#define NOUT  128
#define KE    4224            // K + NOUT (outlier GEMM fused as extra K)

// GEMM tiling (R3 winner shape) + cluster-2 B multicast
#define TM 128
#define TN 256
#define CH_K 64
#define NCHUNK (KE / CH_K)    // 66
#define NSTAGE 4
#define A_STG_BYTES (TM * 128)            // 16384
#define B_STG_BYTES (TN * 128)            // 32768
#define STG_BYTES   (A_STG_BYTES + B_STG_BYTES)   // 49152
#define CTRL_OFF    (NSTAGE * STG_BYTES)          // 196608
#define SMEM_TOTAL  (CTRL_OFF + 128)

#define IDESC ((1u << 4) | ((TN / 8) << 17) | ((TM / 16) << 24))
#define DESC_BASE ((uint64_t(2) << 61) | (uint64_t(1) << 46) | (uint64_t(64) << 32) | (uint64_t(1) << 16))

// Scratch fp16 operands in CHUNK-MAJOR, PRE-SWIZZLED (SW128) layout:
//   byte addr of 16B unit (c, row, u) = ((c*ROWS + row)*128) + ((u ^ (row&7))<<4)
// One CTA-chunk tile is then a single contiguous, MMA-ready block.
__device__ __align__(1024) __half g_Xe[(size_t)NCHUNK * M_DIM * 64];
__device__ __align__(1024) __half g_We[(size_t)NCHUNK * N_DIM * 64];

// ---------------------------------------------------------------------------
// Prep: fp32 -> fp16 (+dequant, outlier fusion) into tiled swizzled layout
// ---------------------------------------------------------------------------
__global__ void prep_x(const float* __restrict__ x) {
    int idx = blockIdx.x * blockDim.x + threadIdx.x;   // (c, m, u): u fastest
    int c  = idx >> 16;            // M_DIM*8 = 65536 units per chunk
    int r  = idx & 65535;
    int m  = r >> 3;
    int u  = r & 7;
    int k0 = c * CH_K + u * 8;
    const float* src = x + (size_t)m * K_DIM + (k0 < K_DIM ? k0 : k0 - NOUT);
    float4 v0 = *(const float4*)src;
    float4 v1 = *(const float4*)(src + 4);
    __half2 h[4];
    h[0] = __floats2half2_rn(v0.x, v0.y);
    h[1] = __floats2half2_rn(v0.z, v0.w);
    h[2] = __floats2half2_rn(v1.x, v1.y);
    h[3] = __floats2half2_rn(v1.z, v1.w);
    char* dst = (char*)g_Xe + ((size_t)c * M_DIM + m) * 128 + ((u ^ (m & 7)) << 4);
    *(uint4*)dst = *(uint4*)h;
}

__global__ void prep_w(const int* __restrict__ qw,
                       const float* __restrict__ scales,
                       const float* __restrict__ zeros,
                       const float* __restrict__ ow) {
    int idx = blockIdx.x * blockDim.x + threadIdx.x;   // (c, n, u)
    int c  = idx >> 15;            // N_DIM*8 = 32768 units per chunk
    int r  = idx & 32767;
    int n  = r >> 3;
    int u  = r & 7;
    int k0 = c * CH_K + u * 8;
    __half2 h[4];
    if (k0 < K_DIM) {
        const int* qp = qw + (size_t)n * K_DIM + k0;
        int4 q0 = *(const int4*)qp;
        int4 q1 = *(const int4*)(qp + 4);
        int g = k0 >> 7;
        float s = scales[g * N_DIM + n];
        float z = zeros[g * N_DIM + n];
        h[0] = __floats2half2_rn((float)q0.x * s + z, (float)q0.y * s + z);
        h[1] = __floats2half2_rn((float)q0.z * s + z, (float)q0.w * s + z);
        h[2] = __floats2half2_rn((float)q1.x * s + z, (float)q1.y * s + z);
        h[3] = __floats2half2_rn((float)q1.z * s + z, (float)q1.w * s + z);
    } else {
        const float* op = ow + (size_t)n * NOUT + (k0 - K_DIM);
        float4 o0 = *(const float4*)op;
        float4 o1 = *(const float4*)(op + 4);
        h[0] = __floats2half2_rn(o0.x, o0.y);
        h[1] = __floats2half2_rn(o0.z, o0.w);
        h[2] = __floats2half2_rn(o1.x, o1.y);
        h[3] = __floats2half2_rn(o1.z, o1.w);
    }
    char* dst = (char*)g_We + ((size_t)c * N_DIM + n) * 128 + ((u ^ (n & 7)) << 4);
    *(uint4*)dst = *(uint4*)h;
}

// ===========================================================================
// Path A: tcgen05 GEMM, warp-specialized, bulk-copy loads + B multicast
// ===========================================================================
#if HAS_TCGEN05
__device__ __forceinline__ uint32_t smem_u32(const void* p) {
    return (uint32_t)__cvta_generic_to_shared(p);
}
__device__ __forceinline__ uint32_t elect_one() {
    uint32_t pred;
    asm volatile("{.reg .pred p; elect.sync _|p, 0xFFFFFFFF; selp.b32 %0, 1, 0, p;}"
                 : "=r"(pred));
    return pred;
}
__device__ __forceinline__ void mma_f16_ss(uint32_t d, uint64_t ad, uint64_t bd,
                                           uint32_t idesc, uint32_t accum) {
    asm volatile(
        "{.reg .pred p; setp.ne.u32 p, %5, 0;\n\t"
        "tcgen05.mma.cta_group::1.kind::f16 [%0], %1, %2, %3, {%4,%4,%4,%4}, p;}\n"
        :: "r"(d), "l"(ad), "l"(bd), "r"(idesc), "r"(0u), "r"(accum) : "memory");
}
__device__ __forceinline__ void mbar_wait(uint32_t addr, uint32_t parity) {
    asm volatile(
        "{.reg .pred P1;\n\t"
        "LAB_WAIT_%=:\n\t"
        "mbarrier.try_wait.parity.acquire.cta.shared::cta.b64 P1, [%0], %1, 0x989680;\n\t"
        "@P1 bra LAB_DONE_%=;\n\t"
        "bra LAB_WAIT_%=;\n\t"
        "LAB_DONE_%=:}\n"
        :: "r"(addr), "r"(parity) : "memory");
}
#endif

extern __shared__ __align__(1024) char smn[];

__global__ void __launch_bounds__(256, 1) __cluster_dims__(1, 2, 1)
gemm_tc(const float* __restrict__ bias, float* __restrict__ y) {
#if HAS_TCGEN05
    const int tid  = threadIdx.x;
    const int w    = tid >> 5;
    const int lane = tid & 31;
    const int bm   = blockIdx.y * TM;
    const int bn   = blockIdx.x * TN;
    uint32_t rank;
    asm("mov.u32 %0, %%cluster_ctarank;" : "=r"(rank));

    const uint32_t sbase    = smem_u32(smn);
    const uint32_t ctrl     = sbase + CTRL_OFF;
    const uint32_t mb_full  = ctrl + 8;                  // 4 x 8B
    const uint32_t mb_empty = ctrl + 8 + 8 * NSTAGE;     // 4 x 8B
    const uint32_t mb_done  = ctrl + 8 + 16 * NSTAGE;

    if (w == 0) {
        asm volatile("tcgen05.alloc.cta_group::1.sync.aligned.shared::cta.b32 [%0], %1;"
                     :: "r"(ctrl), "r"((uint32_t)TN) : "memory");
        asm volatile("tcgen05.relinquish_alloc_permit.cta_group::1.sync.aligned;");
    }
    if (tid == 0) {
#pragma unroll
        for (int s = 0; s < NSTAGE; s++) {
            asm volatile("mbarrier.init.shared.b64 [%0], 1;" :: "r"(mb_full + 8 * s) : "memory");
            asm volatile("mbarrier.init.shared.b64 [%0], 2;" :: "r"(mb_empty + 8 * s) : "memory");
        }
        asm volatile("mbarrier.init.shared.b64 [%0], 1;" :: "r"(mb_done) : "memory");
    }
    __syncthreads();
    // All cluster mbarriers visible before any multicast targets them.
    asm volatile("barrier.cluster.arrive.aligned;" ::: "memory");
    asm volatile("barrier.cluster.wait.aligned;" ::: "memory");

    uint32_t tmem;
    asm volatile("ld.shared.b32 %0, [%1];" : "=r"(tmem) : "r"(ctrl));

    // ---------------- Producer: warp 1, one elected thread --------------
    if (w == 1 && elect_one()) {
        for (int c = 0; c < NCHUNK; c++) {
            const int s = c & (NSTAGE - 1);
            if (c >= NSTAGE)
                mbar_wait(mb_empty + 8 * s, (uint32_t)(((c >> 2) - 1) & 1));
            asm volatile("mbarrier.arrive.expect_tx.shared.b64 _, [%0], %1;"
                         :: "r"(mb_full + 8 * s), "r"((uint32_t)STG_BYTES) : "memory");
            // A: local bulk copy (own 128 rows of this chunk)
            const uint32_t dstA = sbase + s * STG_BYTES;
            const char* srcA = (const char*)g_Xe + ((size_t)c * M_DIM + bm) * 128;
            asm volatile(
                "cp.async.bulk.shared::cluster.global.mbarrier::complete_tx::bytes "
                "[%0], [%1], %2, [%3];"
                :: "r"(dstA), "l"(srcA), "r"((uint32_t)A_STG_BYTES), "r"(mb_full + 8 * s)
                : "memory");
            // B: my half (128 of the 256 shared rows), multicast to both CTAs
            const uint32_t dstB = sbase + s * STG_BYTES + A_STG_BYTES + rank * 16384u;
            const char* srcB = (const char*)g_We + ((size_t)c * N_DIM + bn + rank * 128) * 128;
            asm volatile(
                "cp.async.bulk.shared::cluster.global.mbarrier::complete_tx::bytes"
                ".multicast::cluster [%0], [%1], %2, [%3], %4;"
                :: "r"(dstB), "l"(srcB), "r"(16384u), "r"(mb_full + 8 * s),
                   "h"((uint16_t)0x3) : "memory");
        }
    }

    // ---------------- Consumer: warp 0, one elected thread --------------
    if (w == 0 && elect_one()) {
        asm volatile("tcgen05.fence::after_thread_sync;" ::: "memory");
        for (int c = 0; c < NCHUNK; c++) {
            const int s = c & (NSTAGE - 1);
            mbar_wait(mb_full + 8 * s, (uint32_t)((c >> 2) & 1));
            const uint32_t aAddr = sbase + s * STG_BYTES;
            const uint64_t ad = DESC_BASE | ((aAddr >> 4) & 0x3FFF);
            const uint64_t bd = DESC_BASE | (((aAddr + A_STG_BYTES) >> 4) & 0x3FFF);
#pragma unroll
            for (int kk = 0; kk < 4; kk++)
                mma_f16_ss(tmem, ad + kk * 2, bd + kk * 2, IDESC,
                           (c > 0 || kk > 0) ? 1u : 0u);
            // Buffer-free signal to BOTH CTAs (peer writes into my SMEM).
            asm volatile(
                "tcgen05.commit.cta_group::1.mbarrier::arrive::one.shared::cluster"
                ".multicast::cluster.b64 [%0], %1;"
                :: "r"(mb_empty + 8 * s), "h"((uint16_t)0x3) : "memory");
        }
        // Single-phase completion signal for the epilogue.
        asm volatile(
            "tcgen05.commit.cta_group::1.mbarrier::arrive::one.shared::cluster.b64 [%0];"
            :: "r"(mb_done) : "memory");
    }

    // ---------------- Epilogue: all 8 warps ------------------------------
    mbar_wait(mb_done, 0u);
    asm volatile("tcgen05.fence::after_thread_sync;" ::: "memory");
    {
        const uint32_t warp_off = (uint32_t)((tid & 127) >> 5) << 21;
        const int colBase = (w >> 2) << 7;        // warps 0-3: cols 0..127; 4-7: 128..255
        const int m = bm + ((w & 3) << 5) + lane;
        float* yrow = y + (size_t)m * N_DIM;
#pragma unroll
        for (int cb = 0; cb < 128; cb += 32) {
            uint32_t r[32];
            asm volatile(
                "tcgen05.ld.sync.aligned.32x32b.x32.b32 "
                "{%0,%1,%2,%3,%4,%5,%6,%7,%8,%9,%10,%11,%12,%13,%14,%15,"
                "%16,%17,%18,%19,%20,%21,%22,%23,%24,%25,%26,%27,%28,%29,%30,%31}, [%32];"
                : "=r"(r[0]), "=r"(r[1]), "=r"(r[2]), "=r"(r[3]), "=r"(r[4]), "=r"(r[5]),
                  "=r"(r[6]), "=r"(r[7]), "=r"(r[8]), "=r"(r[9]), "=r"(r[10]), "=r"(r[11]),
                  "=r"(r[12]), "=r"(r[13]), "=r"(r[14]), "=r"(r[15]), "=r"(r[16]), "=r"(r[17]),
                  "=r"(r[18]), "=r"(r[19]), "=r"(r[20]), "=r"(r[21]), "=r"(r[22]), "=r"(r[23]),
                  "=r"(r[24]), "=r"(r[25]), "=r"(r[26]), "=r"(r[27]), "=r"(r[28]), "=r"(r[29]),
                  "=r"(r[30]), "=r"(r[31])
                : "r"(tmem + (uint32_t)(colBase + cb) + warp_off));
            asm volatile("tcgen05.wait::ld.sync.aligned;" ::: "memory");
            const int col0 = bn + colBase + cb;
#pragma unroll
            for (int q = 0; q < 8; q++) {
                float4 bv = *(const float4*)(bias + col0 + q * 4);
                float4 o;
                o.x = __uint_as_float(r[q * 4 + 0]) + bv.x;
                o.y = __uint_as_float(r[q * 4 + 1]) + bv.y;
                o.z = __uint_as_float(r[q * 4 + 2]) + bv.z;
                o.w = __uint_as_float(r[q * 4 + 3]) + bv.w;
                *(float4*)(yrow + col0 + q * 4) = o;
            }
        }
    }

    __syncthreads();
    if (w == 0) {
        asm volatile("tcgen05.dealloc.cta_group::1.sync.aligned.b32 %0, %1;"
                     :: "r"(tmem), "r"((uint32_t)TN));
    }
    // No CTA may exit while peer multicasts targeting its SMEM are in flight.
    asm volatile("barrier.cluster.arrive.aligned;" ::: "memory");
    asm volatile("barrier.cluster.wait.aligned;" ::: "memory");
#endif  // HAS_TCGEN05
}

// ===========================================================================
// Path B: mma.sync fallback (compiled only when tcgen05 is unavailable).
// Reads the tiled pre-swizzled gmem layout.
// ===========================================================================
__global__ __launch_bounds__(256, 2) void gemm_f16(const float* __restrict__ bias,
                                                   float* __restrict__ y) {
#if !HAS_TCGEN05
    __shared__ __align__(16) __half As[3][128 * 32];
    __shared__ __align__(16) __half Bs[3][128 * 32];

    const int t    = threadIdx.x;
    const int lane = t & 31;
    const int w    = t >> 5;
    const int bm   = blockIdx.y << 7;
    const int bn   = blockIdx.x << 7;
    const int wm   = (w >> 2) << 6;
    const int wn   = (w & 3) << 5;

    const int lr = t >> 2;
    const int lc = t & 3;

    float acc[4][4][4];
#pragma unroll
    for (int i = 0; i < 4; i++)
#pragma unroll
        for (int j = 0; j < 4; j++)
#pragma unroll
            for (int r = 0; r < 4; r++) acc[i][j][r] = 0.f;

    unsigned sA = (unsigned)__cvta_generic_to_shared(As);
    unsigned sB = (unsigned)__cvta_generic_to_shared(Bs);

    auto swz = [](int row, int chunk) {
        return (row << 5) + ((chunk ^ ((row >> 1) & 3)) << 3);
    };
    // gmem byte addr of 16B unit (k-step ks, row, lc) in the tiled layout
    auto gaddr = [](const __half* base, int rows_total, int grow, int ks, int u4) {
        int c  = ks >> 1;
        int cu = ((ks & 1) << 2) + u4;
        return (const char*)base + ((size_t)c * rows_total + grow) * 128 +
               ((cu ^ (grow & 7)) << 4);
    };

    auto load_stage = [&](int buf, int ks) {
#pragma unroll
        for (int i = 0; i < 2; i++) {
            int row = lr + (i << 6);
            unsigned da = sA + (unsigned)((buf * 4096 + swz(row, lc)) << 1);
            const char* ga = gaddr(g_Xe, M_DIM, bm + row, ks, lc);
            asm volatile("cp.async.cg.shared.global [%0], [%1], 16;\n" ::"r"(da), "l"(ga));
            unsigned db = sB + (unsigned)((buf * 4096 + swz(row, lc)) << 1);
            const char* gb = gaddr(g_We, N_DIM, bn + row, ks, lc);
            asm volatile("cp.async.cg.shared.global [%0], [%1], 16;\n" ::"r"(db), "l"(gb));
        }
    };

    const int NSTEP = KE / 32;
    load_stage(0, 0);
    asm volatile("cp.async.commit_group;\n");
    load_stage(1, 1);
    asm volatile("cp.async.commit_group;\n");

    const int a_row  = wm + (lane & 15);
    const int a_cofs = lane >> 4;
    const int b_row  = wn + (lane & 7) + ((lane >> 4) << 3);
    const int b_cofs = (lane >> 3) & 1;

    for (int ks = 0; ks < NSTEP; ks++) {
        asm volatile("cp.async.wait_group 1;\n");
        __syncthreads();
        int buf = ks % 3;
        if (ks + 2 < NSTEP) load_stage((ks + 2) % 3, ks + 2);
        asm volatile("cp.async.commit_group;\n");

        unsigned baseA = sA + (unsigned)(buf * 8192);
        unsigned baseB = sB + (unsigned)(buf * 8192);

#pragma unroll
        for (int p = 0; p < 2; p++) {
            unsigned a[4][4];
#pragma unroll
            for (int i = 0; i < 4; i++) {
                int row = a_row + (i << 4);
                int chunk = (p << 1) + a_cofs;
                unsigned addr = baseA + (unsigned)(swz(row, chunk) << 1);
                asm volatile(
                    "ldmatrix.sync.aligned.m8n8.x4.shared.b16 {%0,%1,%2,%3}, [%4];\n"
                    : "=r"(a[i][0]), "=r"(a[i][1]), "=r"(a[i][2]), "=r"(a[i][3])
                    : "r"(addr));
            }
            unsigned b[4][2];
#pragma unroll
            for (int jj = 0; jj < 2; jj++) {
                int row = b_row + (jj << 4);
                int chunk = (p << 1) + b_cofs;
                unsigned addr = baseB + (unsigned)(swz(row, chunk) << 1);
                unsigned r0, r1, r2, r3;
                asm volatile(
                    "ldmatrix.sync.aligned.m8n8.x4.shared.b16 {%0,%1,%2,%3}, [%4];\n"
                    : "=r"(r0), "=r"(r1), "=r"(r2), "=r"(r3)
                    : "r"(addr));
                b[jj * 2][0] = r0; b[jj * 2][1] = r1;
                b[jj * 2 + 1][0] = r2; b[jj * 2 + 1][1] = r3;
            }
#pragma unroll
            for (int i = 0; i < 4; i++)
#pragma unroll
                for (int j = 0; j < 4; j++)
                    asm volatile(
                        "mma.sync.aligned.m16n8k16.row.col.f32.f16.f16.f32 "
                        "{%0,%1,%2,%3}, {%4,%5,%6,%7}, {%8,%9}, {%0,%1,%2,%3};\n"
                        : "+f"(acc[i][j][0]), "+f"(acc[i][j][1]),
                          "+f"(acc[i][j][2]), "+f"(acc[i][j][3])
                        : "r"(a[i][0]), "r"(a[i][1]), "r"(a[i][2]), "r"(a[i][3]),
                          "r"(b[j][0]), "r"(b[j][1]));
        }
    }

#pragma unroll
    for (int i = 0; i < 4; i++) {
        int row = bm + wm + (i << 4) + (lane >> 2);
#pragma unroll
        for (int j = 0; j < 4; j++) {
            int col = bn + wn + (j << 3) + ((lane & 3) << 1);
            float2 bb = *(const float2*)(bias + col);
            float2 o0 = make_float2(acc[i][j][0] + bb.x, acc[i][j][1] + bb.y);
            float2 o1 = make_float2(acc[i][j][2] + bb.x, acc[i][j][3] + bb.y);
            *(float2*)(y + (size_t)row * N_DIM + col)       = o0;
            *(float2*)(y + (size_t)(row + 8) * N_DIM + col) = o1;
        }
    }
#endif  // !HAS_TCGEN05
}

// ---------------------------------------------------------------------------
extern "C" void kernel_launch(void* const* d_in, const int* in_sizes, int n_in,
                              void* d_out, int out_size) {
    const float* x      = (const float*)d_in[0];
    const int*   qw     = (const int*)d_in[1];
    const float* scales = (const float*)d_in[2];
    const float* zeros  = (const float*)d_in[3];
    const float* ow     = (const float*)d_in[4];
    const float* bias   = (const float*)d_in[5];
    float*       y      = (float*)d_out;

    prep_x<<<(NCHUNK * M_DIM * 8) / 256, 256>>>(x);
    prep_w<<<(NCHUNK * N_DIM * 8) / 256, 256>>>(qw, scales, zeros, ow);

    cudaFuncSetAttribute(gemm_tc, cudaFuncAttributeMaxDynamicSharedMemorySize, SMEM_TOTAL);
    dim3 gridT(N_DIM / TN, M_DIM / TM);   // (16, 64); cluster (1,2,1) pairs same-bn CTAs
    gemm_tc<<<gridT, 256, SMEM_TOTAL>>>(bias, y);

    dim3 gridF(N_DIM / 128, M_DIM / 128); // (32, 64)
    gemm_f16<<<gridF, 256>>>(bias, y);
}